// round 1
// baseline (speedup 1.0000x reference)
#include <cuda_runtime.h>
#include <math_constants.h>

// Problem constants (fixed shapes)
#define BB 16
#define CC 512
#define NN 1600
#define HC 64

// Scratch (device globals; no cudaMalloc allowed)
__device__ float g_Q[BB * NN * HC];   // [b][n][h]
__device__ float g_K[BB * NN * HC];   // [b][n][h]
__device__ float g_V[BB * NN * HC];   // [b][n][h]
__device__ float g_R[BB * HC * NN];   // transposed result: [b][h][n]  (== res2 flat)

// ---------------------------------------------------------------------------
// Kernel A: projections.  dst[b,n,h] = sum_c src[b,c,n] * w[c,h]
// src layout: [B, C, N] (n contiguous).  blockIdx.z: 0=Q(rgb,wq) 1=K(rgb,wk) 2=V(hsi,wv)
// ---------------------------------------------------------------------------
__global__ __launch_bounds__(256) void proj_kernel(
    const float* __restrict__ rgb, const float* __restrict__ hsi,
    const float* __restrict__ wq, const float* __restrict__ wk,
    const float* __restrict__ wv)
{
    const int n0 = blockIdx.x * 64;
    const int b  = blockIdx.y;
    const int which = blockIdx.z;
    const float* src = (which == 2) ? hsi : rgb;
    const float* w   = (which == 0) ? wq : (which == 1) ? wk : wv;
    float* dst       = (which == 0) ? g_Q : (which == 1) ? g_K : g_V;

    __shared__ float As[32][64];   // As[k][n] = src[b][c0+k][n0+n]
    __shared__ float Ws[32][64];   // Ws[k][h] = w[c0+k][h]

    const int tid = threadIdx.x;
    const int tx = tid & 15, ty = tid >> 4;

    float acc[4][4] = {};
    const float* srcb = src + (size_t)b * CC * NN;

    for (int c0 = 0; c0 < CC; c0 += 32) {
        #pragma unroll
        for (int idx = tid; idx < 2048; idx += 256) {
            int k = idx >> 6, n = idx & 63;
            As[k][n] = srcb[(size_t)(c0 + k) * NN + n0 + n];
            Ws[k][n] = w[(c0 + k) * HC + n];
        }
        __syncthreads();
        #pragma unroll
        for (int k = 0; k < 32; k++) {
            float a[4], bv[4];
            #pragma unroll
            for (int i = 0; i < 4; i++) a[i] = As[k][4 * ty + i];
            #pragma unroll
            for (int j = 0; j < 4; j++) bv[j] = Ws[k][4 * tx + j];
            #pragma unroll
            for (int i = 0; i < 4; i++)
                #pragma unroll
                for (int j = 0; j < 4; j++)
                    acc[i][j] = fmaf(a[i], bv[j], acc[i][j]);
        }
        __syncthreads();
    }
    #pragma unroll
    for (int i = 0; i < 4; i++) {
        int n = n0 + 4 * ty + i;
        float4 v = make_float4(acc[i][0], acc[i][1], acc[i][2], acc[i][3]);
        *(float4*)&dst[((size_t)b * NN + n) * HC + 4 * tx] = v;
    }
}

// ---------------------------------------------------------------------------
// Kernel B: flash-style attention per (batch, 64-query tile).
// S = Q K^T * (1/8), online softmax, acc = P V.  Result written TRANSPOSED:
// g_R[b][h][n] = res[b][n][h]   (this realizes the reshape trick for free)
// ---------------------------------------------------------------------------
#define LDS_STRIDE 68

__global__ __launch_bounds__(256) void attn_kernel()
{
    const int n0 = blockIdx.x * 64;
    const int b  = blockIdx.y;

    extern __shared__ float sm[];
    float* Qs  = sm;                       // [64][68]
    float* KPs = sm + 64 * LDS_STRIDE;     // [64][68]  K tile, then reused for P
    float* Vs  = sm + 2 * 64 * LDS_STRIDE; // [64][68]

    const int tid = threadIdx.x;
    const int tx = tid & 15, ty = tid >> 4;

    const float* Qb = g_Q + ((size_t)b * NN + n0) * HC;
    for (int idx = tid; idx < 4096; idx += 256) {
        int r = idx >> 6, h = idx & 63;
        Qs[r * LDS_STRIDE + h] = Qb[r * HC + h];
    }

    float row_max[4], row_sum[4], acc[4][4] = {};
    #pragma unroll
    for (int i = 0; i < 4; i++) { row_max[i] = -CUDART_INF_F; row_sum[i] = 0.f; }

    const float* Kb = g_K + (size_t)b * NN * HC;
    const float* Vb = g_V + (size_t)b * NN * HC;

    for (int m0 = 0; m0 < NN; m0 += 64) {
        __syncthreads();  // prior PV reads done (and Qs visible on first iter)
        for (int idx = tid; idx < 4096; idx += 256) {
            int r = idx >> 6, h = idx & 63;
            KPs[r * LDS_STRIDE + h] = Kb[(size_t)(m0 + r) * HC + h];
            Vs[r * LDS_STRIDE + h]  = Vb[(size_t)(m0 + r) * HC + h];
        }
        __syncthreads();

        // S tile: s[i][j] = q(row 4ty+i) . k(row 4tx+j)
        float s[4][4] = {};
        #pragma unroll 16
        for (int h = 0; h < 64; h++) {
            float a[4], bv[4];
            #pragma unroll
            for (int i = 0; i < 4; i++) a[i] = Qs[(4 * ty + i) * LDS_STRIDE + h];
            #pragma unroll
            for (int j = 0; j < 4; j++) bv[j] = KPs[(4 * tx + j) * LDS_STRIDE + h];
            #pragma unroll
            for (int i = 0; i < 4; i++)
                #pragma unroll
                for (int j = 0; j < 4; j++)
                    s[i][j] = fmaf(a[i], bv[j], s[i][j]);
        }

        // online softmax (rows reduced across the 16 tx lanes)
        #pragma unroll
        for (int i = 0; i < 4; i++) {
            float m = fmaxf(fmaxf(s[i][0], s[i][1]), fmaxf(s[i][2], s[i][3])) * 0.125f;
            #pragma unroll
            for (int off = 8; off >= 1; off >>= 1)
                m = fmaxf(m, __shfl_xor_sync(0xffffffffu, m, off, 16));
            float nm = fmaxf(row_max[i], m);
            float factor = __expf(row_max[i] - nm);
            row_max[i] = nm;
            float ps = 0.f;
            #pragma unroll
            for (int j = 0; j < 4; j++) {
                s[i][j] = __expf(fmaf(s[i][j], 0.125f, -nm));
                ps += s[i][j];
            }
            #pragma unroll
            for (int off = 8; off >= 1; off >>= 1)
                ps += __shfl_xor_sync(0xffffffffu, ps, off, 16);
            row_sum[i] = row_sum[i] * factor + ps;
            #pragma unroll
            for (int j = 0; j < 4; j++) acc[i][j] *= factor;
        }

        __syncthreads();  // everyone done reading KPs as K
        #pragma unroll
        for (int i = 0; i < 4; i++)
            #pragma unroll
            for (int j = 0; j < 4; j++)
                KPs[(4 * ty + i) * LDS_STRIDE + 4 * tx + j] = s[i][j];
        __syncthreads();

        // acc += P @ V
        #pragma unroll 16
        for (int k = 0; k < 64; k++) {
            float a[4], bv[4];
            #pragma unroll
            for (int i = 0; i < 4; i++) a[i] = KPs[(4 * ty + i) * LDS_STRIDE + k];
            #pragma unroll
            for (int j = 0; j < 4; j++) bv[j] = Vs[k * LDS_STRIDE + 4 * tx + j];
            #pragma unroll
            for (int i = 0; i < 4; i++)
                #pragma unroll
                for (int j = 0; j < 4; j++)
                    acc[i][j] = fmaf(a[i], bv[j], acc[i][j]);
        }
    }

    // finalize + transposed store
    float* Rb = g_R + (size_t)b * HC * NN;
    #pragma unroll
    for (int i = 0; i < 4; i++) {
        float inv = 1.f / row_sum[i];
        int n = n0 + 4 * ty + i;
        #pragma unroll
        for (int j = 0; j < 4; j++)
            Rb[(size_t)(4 * tx + j) * NN + n] = acc[i][j] * inv;
    }
}

// ---------------------------------------------------------------------------
// Kernel C: out[b,c,n] = sum_k res2[b,n,k] * wo[k,c]
// res2[b][n][k] = g_R flat (b) at index n*HC + k
// ---------------------------------------------------------------------------
__global__ __launch_bounds__(256) void out_kernel(
    const float* __restrict__ wo, float* __restrict__ out)
{
    const int n0 = blockIdx.x * 64;
    const int c0 = blockIdx.y * 64;
    const int b  = blockIdx.z;

    __shared__ float Rs[64][65];
    __shared__ float Ws[64][64];
    __shared__ float Os[64][65];

    const int tid = threadIdx.x;
    const int tx = tid & 15, ty = tid >> 4;

    const float* Rb = g_R + (size_t)b * NN * HC;  // viewed as [N][HC]
    for (int idx = tid; idx < 4096; idx += 256) {
        int r = idx >> 6, k = idx & 63;
        Rs[r][k] = Rb[(size_t)(n0 + r) * HC + k];
        Ws[r][k] = wo[r * CC + c0 + k];           // r = hc index, k = c index
    }
    __syncthreads();

    float acc[4][4] = {};
    #pragma unroll 16
    for (int k = 0; k < 64; k++) {
        float a[4], bv[4];
        #pragma unroll
        for (int i = 0; i < 4; i++) a[i] = Rs[4 * ty + i][k];
        #pragma unroll
        for (int j = 0; j < 4; j++) bv[j] = Ws[k][4 * tx + j];
        #pragma unroll
        for (int i = 0; i < 4; i++)
            #pragma unroll
            for (int j = 0; j < 4; j++)
                acc[i][j] = fmaf(a[i], bv[j], acc[i][j]);
    }
    #pragma unroll
    for (int i = 0; i < 4; i++)
        #pragma unroll
        for (int j = 0; j < 4; j++)
            Os[4 * ty + i][4 * tx + j] = acc[i][j];
    __syncthreads();

    float* ob = out + (size_t)b * CC * NN;
    for (int idx = tid; idx < 4096; idx += 256) {
        int cc = idx >> 6, nn = idx & 63;
        ob[(size_t)(c0 + cc) * NN + n0 + nn] = Os[nn][cc];
    }
}

// ---------------------------------------------------------------------------
extern "C" void kernel_launch(void* const* d_in, const int* in_sizes, int n_in,
                              void* d_out, int out_size)
{
    const float* rgb = (const float*)d_in[0];
    const float* hsi = (const float*)d_in[1];
    const float* wq  = (const float*)d_in[2];
    const float* wk  = (const float*)d_in[3];
    const float* wv  = (const float*)d_in[4];
    const float* wo  = (const float*)d_in[5];
    float* out = (float*)d_out;

    const int smemB = 3 * 64 * LDS_STRIDE * sizeof(float);  // 52224 B
    cudaFuncSetAttribute(attn_kernel, cudaFuncAttributeMaxDynamicSharedMemorySize, smemB);

    proj_kernel<<<dim3(NN / 64, BB, 3), 256>>>(rgb, hsi, wq, wk, wv);
    attn_kernel<<<dim3(NN / 64, BB), 256, smemB>>>();
    out_kernel<<<dim3(NN / 64, CC / 64, BB), 256>>>(wo, out);
}

// round 2
// speedup vs baseline: 1.0000x; 1.0000x over previous
#include <cuda_runtime.h>
#include <math_constants.h>

// Problem constants (fixed shapes)
#define BB 16
#define CC 512
#define NN 1600
#define HC 64

// Scratch (device globals; no cudaMalloc allowed)
__device__ float g_Q[BB * NN * HC];   // [b][n][h]
__device__ float g_K[BB * NN * HC];   // [b][n][h]
__device__ float g_V[BB * NN * HC];   // [b][n][h]
__device__ float g_R[BB * HC * NN];   // transposed result: [b][h][n]  (== res2 flat)

// ---------------------------------------------------------------------------
// Kernel A: projections.  dst[b,n,h] = sum_c src[b,c,n] * w[c,h]
// src layout: [B, C, N] (n contiguous).  blockIdx.z: 0=Q(rgb,wq) 1=K(rgb,wk) 2=V(hsi,wv)
// ---------------------------------------------------------------------------
__global__ __launch_bounds__(256) void proj_kernel(
    const float* __restrict__ rgb, const float* __restrict__ hsi,
    const float* __restrict__ wq, const float* __restrict__ wk,
    const float* __restrict__ wv)
{
    const int n0 = blockIdx.x * 64;
    const int b  = blockIdx.y;
    const int which = blockIdx.z;
    const float* src = (which == 2) ? hsi : rgb;
    const float* w   = (which == 0) ? wq : (which == 1) ? wk : wv;
    float* dst       = (which == 0) ? g_Q : (which == 1) ? g_K : g_V;

    __shared__ float As[32][64];   // As[k][n] = src[b][c0+k][n0+n]
    __shared__ float Ws[32][64];   // Ws[k][h] = w[c0+k][h]

    const int tid = threadIdx.x;
    const int tx = tid & 15, ty = tid >> 4;

    float acc[4][4] = {};
    const float* srcb = src + (size_t)b * CC * NN;

    for (int c0 = 0; c0 < CC; c0 += 32) {
        #pragma unroll
        for (int idx = tid; idx < 2048; idx += 256) {
            int k = idx >> 6, n = idx & 63;
            As[k][n] = srcb[(size_t)(c0 + k) * NN + n0 + n];
            Ws[k][n] = w[(c0 + k) * HC + n];
        }
        __syncthreads();
        #pragma unroll
        for (int k = 0; k < 32; k++) {
            float a[4], bv[4];
            #pragma unroll
            for (int i = 0; i < 4; i++) a[i] = As[k][4 * ty + i];
            #pragma unroll
            for (int j = 0; j < 4; j++) bv[j] = Ws[k][4 * tx + j];
            #pragma unroll
            for (int i = 0; i < 4; i++)
                #pragma unroll
                for (int j = 0; j < 4; j++)
                    acc[i][j] = fmaf(a[i], bv[j], acc[i][j]);
        }
        __syncthreads();
    }
    #pragma unroll
    for (int i = 0; i < 4; i++) {
        int n = n0 + 4 * ty + i;
        float4 v = make_float4(acc[i][0], acc[i][1], acc[i][2], acc[i][3]);
        *(float4*)&dst[((size_t)b * NN + n) * HC + 4 * tx] = v;
    }
}

// ---------------------------------------------------------------------------
// Kernel B: flash-style attention per (batch, 64-query tile).
// S = Q K^T * (1/8), online softmax, acc = P V.  Result written TRANSPOSED:
// g_R[b][h][n] = res[b][n][h]   (this realizes the reshape trick for free)
// ---------------------------------------------------------------------------
#define LDS_STRIDE 68

__global__ __launch_bounds__(256) void attn_kernel()
{
    const int n0 = blockIdx.x * 64;
    const int b  = blockIdx.y;

    extern __shared__ float sm[];
    float* Qs  = sm;                       // [64][68]
    float* KPs = sm + 64 * LDS_STRIDE;     // [64][68]  K tile, then reused for P
    float* Vs  = sm + 2 * 64 * LDS_STRIDE; // [64][68]

    const int tid = threadIdx.x;
    const int tx = tid & 15, ty = tid >> 4;

    const float* Qb = g_Q + ((size_t)b * NN + n0) * HC;
    for (int idx = tid; idx < 4096; idx += 256) {
        int r = idx >> 6, h = idx & 63;
        Qs[r * LDS_STRIDE + h] = Qb[r * HC + h];
    }

    float row_max[4], row_sum[4], acc[4][4] = {};
    #pragma unroll
    for (int i = 0; i < 4; i++) { row_max[i] = -CUDART_INF_F; row_sum[i] = 0.f; }

    const float* Kb = g_K + (size_t)b * NN * HC;
    const float* Vb = g_V + (size_t)b * NN * HC;

    for (int m0 = 0; m0 < NN; m0 += 64) {
        __syncthreads();  // prior PV reads done (and Qs visible on first iter)
        for (int idx = tid; idx < 4096; idx += 256) {
            int r = idx >> 6, h = idx & 63;
            KPs[r * LDS_STRIDE + h] = Kb[(size_t)(m0 + r) * HC + h];
            Vs[r * LDS_STRIDE + h]  = Vb[(size_t)(m0 + r) * HC + h];
        }
        __syncthreads();

        // S tile: s[i][j] = q(row 4ty+i) . k(row 4tx+j)
        float s[4][4] = {};
        #pragma unroll 16
        for (int h = 0; h < 64; h++) {
            float a[4], bv[4];
            #pragma unroll
            for (int i = 0; i < 4; i++) a[i] = Qs[(4 * ty + i) * LDS_STRIDE + h];
            #pragma unroll
            for (int j = 0; j < 4; j++) bv[j] = KPs[(4 * tx + j) * LDS_STRIDE + h];
            #pragma unroll
            for (int i = 0; i < 4; i++)
                #pragma unroll
                for (int j = 0; j < 4; j++)
                    s[i][j] = fmaf(a[i], bv[j], s[i][j]);
        }

        // online softmax (rows reduced across the 16 tx lanes)
        #pragma unroll
        for (int i = 0; i < 4; i++) {
            float m = fmaxf(fmaxf(s[i][0], s[i][1]), fmaxf(s[i][2], s[i][3])) * 0.125f;
            #pragma unroll
            for (int off = 8; off >= 1; off >>= 1)
                m = fmaxf(m, __shfl_xor_sync(0xffffffffu, m, off, 16));
            float nm = fmaxf(row_max[i], m);
            float factor = __expf(row_max[i] - nm);
            row_max[i] = nm;
            float ps = 0.f;
            #pragma unroll
            for (int j = 0; j < 4; j++) {
                s[i][j] = __expf(fmaf(s[i][j], 0.125f, -nm));
                ps += s[i][j];
            }
            #pragma unroll
            for (int off = 8; off >= 1; off >>= 1)
                ps += __shfl_xor_sync(0xffffffffu, ps, off, 16);
            row_sum[i] = row_sum[i] * factor + ps;
            #pragma unroll
            for (int j = 0; j < 4; j++) acc[i][j] *= factor;
        }

        __syncthreads();  // everyone done reading KPs as K
        #pragma unroll
        for (int i = 0; i < 4; i++)
            #pragma unroll
            for (int j = 0; j < 4; j++)
                KPs[(4 * ty + i) * LDS_STRIDE + 4 * tx + j] = s[i][j];
        __syncthreads();

        // acc += P @ V
        #pragma unroll 16
        for (int k = 0; k < 64; k++) {
            float a[4], bv[4];
            #pragma unroll
            for (int i = 0; i < 4; i++) a[i] = KPs[(4 * ty + i) * LDS_STRIDE + k];
            #pragma unroll
            for (int j = 0; j < 4; j++) bv[j] = Vs[k * LDS_STRIDE + 4 * tx + j];
            #pragma unroll
            for (int i = 0; i < 4; i++)
                #pragma unroll
                for (int j = 0; j < 4; j++)
                    acc[i][j] = fmaf(a[i], bv[j], acc[i][j]);
        }
    }

    // finalize + transposed store
    float* Rb = g_R + (size_t)b * HC * NN;
    #pragma unroll
    for (int i = 0; i < 4; i++) {
        float inv = 1.f / row_sum[i];
        int n = n0 + 4 * ty + i;
        #pragma unroll
        for (int j = 0; j < 4; j++)
            Rb[(size_t)(4 * tx + j) * NN + n] = acc[i][j] * inv;
    }
}

// ---------------------------------------------------------------------------
// Kernel C: out[b,c,n] = sum_k res2[b,n,k] * wo[k,c]
// res2[b][n][k] = g_R flat (b) at index n*HC + k
// ---------------------------------------------------------------------------
__global__ __launch_bounds__(256) void out_kernel(
    const float* __restrict__ wo, float* __restrict__ out)
{
    const int n0 = blockIdx.x * 64;
    const int c0 = blockIdx.y * 64;
    const int b  = blockIdx.z;

    __shared__ float Rs[64][65];
    __shared__ float Ws[64][64];
    __shared__ float Os[64][65];

    const int tid = threadIdx.x;
    const int tx = tid & 15, ty = tid >> 4;

    const float* Rb = g_R + (size_t)b * NN * HC;  // viewed as [N][HC]
    for (int idx = tid; idx < 4096; idx += 256) {
        int r = idx >> 6, k = idx & 63;
        Rs[r][k] = Rb[(size_t)(n0 + r) * HC + k];
        Ws[r][k] = wo[r * CC + c0 + k];           // r = hc index, k = c index
    }
    __syncthreads();

    float acc[4][4] = {};
    #pragma unroll 16
    for (int k = 0; k < 64; k++) {
        float a[4], bv[4];
        #pragma unroll
        for (int i = 0; i < 4; i++) a[i] = Rs[4 * ty + i][k];
        #pragma unroll
        for (int j = 0; j < 4; j++) bv[j] = Ws[k][4 * tx + j];
        #pragma unroll
        for (int i = 0; i < 4; i++)
            #pragma unroll
            for (int j = 0; j < 4; j++)
                acc[i][j] = fmaf(a[i], bv[j], acc[i][j]);
    }
    #pragma unroll
    for (int i = 0; i < 4; i++)
        #pragma unroll
        for (int j = 0; j < 4; j++)
            Os[4 * ty + i][4 * tx + j] = acc[i][j];
    __syncthreads();

    float* ob = out + (size_t)b * CC * NN;
    for (int idx = tid; idx < 4096; idx += 256) {
        int cc = idx >> 6, nn = idx & 63;
        ob[(size_t)(c0 + cc) * NN + n0 + nn] = Os[nn][cc];
    }
}

// ---------------------------------------------------------------------------
extern "C" void kernel_launch(void* const* d_in, const int* in_sizes, int n_in,
                              void* d_out, int out_size)
{
    const float* rgb = (const float*)d_in[0];
    const float* hsi = (const float*)d_in[1];
    const float* wq  = (const float*)d_in[2];
    const float* wk  = (const float*)d_in[3];
    const float* wv  = (const float*)d_in[4];
    const float* wo  = (const float*)d_in[5];
    float* out = (float*)d_out;

    const int smemB = 3 * 64 * LDS_STRIDE * sizeof(float);  // 52224 B
    cudaFuncSetAttribute(attn_kernel, cudaFuncAttributeMaxDynamicSharedMemorySize, smemB);

    proj_kernel<<<dim3(NN / 64, BB, 3), 256>>>(rgb, hsi, wq, wk, wv);
    attn_kernel<<<dim3(NN / 64, BB), 256, smemB>>>();
    out_kernel<<<dim3(NN / 64, CC / 64, BB), 256>>>(wo, out);
}

// round 3
// speedup vs baseline: 1.0010x; 1.0009x over previous
#include <cuda_runtime.h>
#include <math_constants.h>

// Problem constants (fixed shapes)
#define BB 16
#define CC 512
#define NN 1600
#define HC 64

// Scratch (device globals; no cudaMalloc allowed)
__device__ float g_Q[BB * NN * HC];   // [b][n][h]
__device__ float g_K[BB * NN * HC];   // [b][n][h]
__device__ float g_V[BB * NN * HC];   // [b][n][h]
__device__ float g_R[BB * HC * NN];   // transposed result: [b][h][n]  (== res2 flat)

// ---------------------------------------------------------------------------
// Kernel A: projections.  dst[b,n,h] = sum_c src[b,c,n] * w[c,h]
// src layout: [B, C, N] (n contiguous).  blockIdx.z: 0=Q(rgb,wq) 1=K(rgb,wk) 2=V(hsi,wv)
// ---------------------------------------------------------------------------
__global__ __launch_bounds__(256) void proj_kernel(
    const float* __restrict__ rgb, const float* __restrict__ hsi,
    const float* __restrict__ wq, const float* __restrict__ wk,
    const float* __restrict__ wv)
{
    const int n0 = blockIdx.x * 64;
    const int b  = blockIdx.y;
    const int which = blockIdx.z;
    const float* src = (which == 2) ? hsi : rgb;
    const float* w   = (which == 0) ? wq : (which == 1) ? wk : wv;
    float* dst       = (which == 0) ? g_Q : (which == 1) ? g_K : g_V;

    __shared__ float As[32][64];   // As[k][n] = src[b][c0+k][n0+n]
    __shared__ float Ws[32][64];   // Ws[k][h] = w[c0+k][h]

    const int tid = threadIdx.x;
    const int tx = tid & 15, ty = tid >> 4;

    float acc[4][4] = {};
    const float* srcb = src + (size_t)b * CC * NN;

    for (int c0 = 0; c0 < CC; c0 += 32) {
        #pragma unroll
        for (int idx = tid; idx < 2048; idx += 256) {
            int k = idx >> 6, n = idx & 63;
            As[k][n] = srcb[(size_t)(c0 + k) * NN + n0 + n];
            Ws[k][n] = w[(c0 + k) * HC + n];
        }
        __syncthreads();
        #pragma unroll
        for (int k = 0; k < 32; k++) {
            float a[4], bv[4];
            #pragma unroll
            for (int i = 0; i < 4; i++) a[i] = As[k][4 * ty + i];
            #pragma unroll
            for (int j = 0; j < 4; j++) bv[j] = Ws[k][4 * tx + j];
            #pragma unroll
            for (int i = 0; i < 4; i++)
                #pragma unroll
                for (int j = 0; j < 4; j++)
                    acc[i][j] = fmaf(a[i], bv[j], acc[i][j]);
        }
        __syncthreads();
    }
    #pragma unroll
    for (int i = 0; i < 4; i++) {
        int n = n0 + 4 * ty + i;
        float4 v = make_float4(acc[i][0], acc[i][1], acc[i][2], acc[i][3]);
        *(float4*)&dst[((size_t)b * NN + n) * HC + 4 * tx] = v;
    }
}

// ---------------------------------------------------------------------------
// Kernel B: flash-style attention per (batch, 64-query tile).
// S = Q K^T * (1/8), online softmax, acc = P V.  Result written TRANSPOSED:
// g_R[b][h][n] = res[b][n][h]   (this realizes the reshape trick for free)
// ---------------------------------------------------------------------------
#define LDS_STRIDE 68

__global__ __launch_bounds__(256) void attn_kernel()
{
    const int n0 = blockIdx.x * 64;
    const int b  = blockIdx.y;

    extern __shared__ float sm[];
    float* Qs  = sm;                       // [64][68]
    float* KPs = sm + 64 * LDS_STRIDE;     // [64][68]  K tile, then reused for P
    float* Vs  = sm + 2 * 64 * LDS_STRIDE; // [64][68]

    const int tid = threadIdx.x;
    const int tx = tid & 15, ty = tid >> 4;

    const float* Qb = g_Q + ((size_t)b * NN + n0) * HC;
    for (int idx = tid; idx < 4096; idx += 256) {
        int r = idx >> 6, h = idx & 63;
        Qs[r * LDS_STRIDE + h] = Qb[r * HC + h];
    }

    float row_max[4], row_sum[4], acc[4][4] = {};
    #pragma unroll
    for (int i = 0; i < 4; i++) { row_max[i] = -CUDART_INF_F; row_sum[i] = 0.f; }

    const float* Kb = g_K + (size_t)b * NN * HC;
    const float* Vb = g_V + (size_t)b * NN * HC;

    for (int m0 = 0; m0 < NN; m0 += 64) {
        __syncthreads();  // prior PV reads done (and Qs visible on first iter)
        for (int idx = tid; idx < 4096; idx += 256) {
            int r = idx >> 6, h = idx & 63;
            KPs[r * LDS_STRIDE + h] = Kb[(size_t)(m0 + r) * HC + h];
            Vs[r * LDS_STRIDE + h]  = Vb[(size_t)(m0 + r) * HC + h];
        }
        __syncthreads();

        // S tile: s[i][j] = q(row 4ty+i) . k(row 4tx+j)
        float s[4][4] = {};
        #pragma unroll 16
        for (int h = 0; h < 64; h++) {
            float a[4], bv[4];
            #pragma unroll
            for (int i = 0; i < 4; i++) a[i] = Qs[(4 * ty + i) * LDS_STRIDE + h];
            #pragma unroll
            for (int j = 0; j < 4; j++) bv[j] = KPs[(4 * tx + j) * LDS_STRIDE + h];
            #pragma unroll
            for (int i = 0; i < 4; i++)
                #pragma unroll
                for (int j = 0; j < 4; j++)
                    s[i][j] = fmaf(a[i], bv[j], s[i][j]);
        }

        // online softmax (rows reduced across the 16 tx lanes)
        #pragma unroll
        for (int i = 0; i < 4; i++) {
            float m = fmaxf(fmaxf(s[i][0], s[i][1]), fmaxf(s[i][2], s[i][3])) * 0.125f;
            #pragma unroll
            for (int off = 8; off >= 1; off >>= 1)
                m = fmaxf(m, __shfl_xor_sync(0xffffffffu, m, off, 16));
            float nm = fmaxf(row_max[i], m);
            float factor = __expf(row_max[i] - nm);
            row_max[i] = nm;
            float ps = 0.f;
            #pragma unroll
            for (int j = 0; j < 4; j++) {
                s[i][j] = __expf(fmaf(s[i][j], 0.125f, -nm));
                ps += s[i][j];
            }
            #pragma unroll
            for (int off = 8; off >= 1; off >>= 1)
                ps += __shfl_xor_sync(0xffffffffu, ps, off, 16);
            row_sum[i] = row_sum[i] * factor + ps;
            #pragma unroll
            for (int j = 0; j < 4; j++) acc[i][j] *= factor;
        }

        __syncthreads();  // everyone done reading KPs as K
        #pragma unroll
        for (int i = 0; i < 4; i++)
            #pragma unroll
            for (int j = 0; j < 4; j++)
                KPs[(4 * ty + i) * LDS_STRIDE + 4 * tx + j] = s[i][j];
        __syncthreads();

        // acc += P @ V
        #pragma unroll 16
        for (int k = 0; k < 64; k++) {
            float a[4], bv[4];
            #pragma unroll
            for (int i = 0; i < 4; i++) a[i] = KPs[(4 * ty + i) * LDS_STRIDE + k];
            #pragma unroll
            for (int j = 0; j < 4; j++) bv[j] = Vs[k * LDS_STRIDE + 4 * tx + j];
            #pragma unroll
            for (int i = 0; i < 4; i++)
                #pragma unroll
                for (int j = 0; j < 4; j++)
                    acc[i][j] = fmaf(a[i], bv[j], acc[i][j]);
        }
    }

    // finalize + transposed store
    float* Rb = g_R + (size_t)b * HC * NN;
    #pragma unroll
    for (int i = 0; i < 4; i++) {
        float inv = 1.f / row_sum[i];
        int n = n0 + 4 * ty + i;
        #pragma unroll
        for (int j = 0; j < 4; j++)
            Rb[(size_t)(4 * tx + j) * NN + n] = acc[i][j] * inv;
    }
}

// ---------------------------------------------------------------------------
// Kernel C: out[b,c,n] = sum_k res2[b,n,k] * wo[k,c]
// res2[b][n][k] = g_R flat (b) at index n*HC + k
// ---------------------------------------------------------------------------
__global__ __launch_bounds__(256) void out_kernel(
    const float* __restrict__ wo, float* __restrict__ out)
{
    const int n0 = blockIdx.x * 64;
    const int c0 = blockIdx.y * 64;
    const int b  = blockIdx.z;

    __shared__ float Rs[64][65];
    __shared__ float Ws[64][64];
    __shared__ float Os[64][65];

    const int tid = threadIdx.x;
    const int tx = tid & 15, ty = tid >> 4;

    const float* Rb = g_R + (size_t)b * NN * HC;  // viewed as [N][HC]
    for (int idx = tid; idx < 4096; idx += 256) {
        int r = idx >> 6, k = idx & 63;
        Rs[r][k] = Rb[(size_t)(n0 + r) * HC + k];
        Ws[r][k] = wo[r * CC + c0 + k];           // r = hc index, k = c index
    }
    __syncthreads();

    float acc[4][4] = {};
    #pragma unroll 16
    for (int k = 0; k < 64; k++) {
        float a[4], bv[4];
        #pragma unroll
        for (int i = 0; i < 4; i++) a[i] = Rs[4 * ty + i][k];
        #pragma unroll
        for (int j = 0; j < 4; j++) bv[j] = Ws[k][4 * tx + j];
        #pragma unroll
        for (int i = 0; i < 4; i++)
            #pragma unroll
            for (int j = 0; j < 4; j++)
                acc[i][j] = fmaf(a[i], bv[j], acc[i][j]);
    }
    #pragma unroll
    for (int i = 0; i < 4; i++)
        #pragma unroll
        for (int j = 0; j < 4; j++)
            Os[4 * ty + i][4 * tx + j] = acc[i][j];
    __syncthreads();

    float* ob = out + (size_t)b * CC * NN;
    for (int idx = tid; idx < 4096; idx += 256) {
        int cc = idx >> 6, nn = idx & 63;
        ob[(size_t)(c0 + cc) * NN + n0 + nn] = Os[nn][cc];
    }
}

// ---------------------------------------------------------------------------
extern "C" void kernel_launch(void* const* d_in, const int* in_sizes, int n_in,
                              void* d_out, int out_size)
{
    const float* rgb = (const float*)d_in[0];
    const float* hsi = (const float*)d_in[1];
    const float* wq  = (const float*)d_in[2];
    const float* wk  = (const float*)d_in[3];
    const float* wv  = (const float*)d_in[4];
    const float* wo  = (const float*)d_in[5];
    float* out = (float*)d_out;

    const int smemB = 3 * 64 * LDS_STRIDE * sizeof(float);  // 52224 B
    cudaFuncSetAttribute(attn_kernel, cudaFuncAttributeMaxDynamicSharedMemorySize, smemB);

    proj_kernel<<<dim3(NN / 64, BB, 3), 256>>>(rgb, hsi, wq, wk, wv);
    attn_kernel<<<dim3(NN / 64, BB), 256, smemB>>>();
    out_kernel<<<dim3(NN / 64, CC / 64, BB), 256>>>(wo, out);
}

// round 5
// speedup vs baseline: 1.2244x; 1.2232x over previous
#include <cuda_runtime.h>
#include <cuda_bf16.h>
#include <mma.h>
using namespace nvcuda;

#define BB 16
#define CC 512
#define NN 1600
#define HC 64
#define L2E8 0.1803368801111204f

typedef unsigned int u32; typedef unsigned short u16;

// scratch (device globals; no cudaMalloc allowed)
__device__ u32 g_Q[BB*NN*HC];              // [b][n][h] packed (hi16|lo16)
__device__ u32 g_K[BB*NN*HC];              // [b][m][h]
__device__ u32 g_V[BB*NN*HC];              // [b][m][h]
__device__ u32 g_R[BB*NN*HC];              // [b][h][n]  (== res2 flat, reshape trick)
__device__ u16 g_Wh[3*CC*HC], g_Wl[3*CC*HC];  // [which][c][h] bf16 hi/lo planes
__device__ u16 g_Woh[HC*CC],  g_Wol[HC*CC];   // [k][c]

// fp32 -> packed: low16 = truncated bf16 (hi), high16 = rn-bf16 of residual (lo)
__device__ __forceinline__ u32 pack_hl(float x){
    u32 h=__float_as_uint(x)&0xffff0000u; u16 lb;
    asm("cvt.rn.bf16.f32 %0,%1;":"=h"(lb):"f"(x-__uint_as_float(h)));
    return (h>>16)|((u32)lb<<16);
}
__device__ __forceinline__ float ex2f(float x){float r;asm("ex2.approx.ftz.f32 %0,%1;":"=f"(r):"f"(x));return r;}

typedef wmma::fragment<wmma::matrix_a,16,16,16,__nv_bfloat16,wmma::row_major> FragA;
typedef wmma::fragment<wmma::matrix_b,16,16,16,__nv_bfloat16,wmma::row_major> FragB;
typedef wmma::fragment<wmma::matrix_b,16,16,16,__nv_bfloat16,wmma::col_major> FragBc;
typedef wmma::fragment<wmma::accumulator,16,16,16,float> FragC;
#define BF16P(p) reinterpret_cast<const __nv_bfloat16*>(p)

// 3-pass split mma: acc += hi*hi + lo*hi + hi*lo
#define MMA3(acc, ah, al, bh, bl) do { \
    wmma::mma_sync(acc, ah, bh, acc);  \
    wmma::mma_sync(acc, al, bh, acc);  \
    wmma::mma_sync(acc, ah, bl, acc);  } while(0)

// ---------------- prep: split weights into bf16 hi/lo planes ----------------
__global__ void prep_kernel(const float* __restrict__ wq,const float* __restrict__ wk,
                            const float* __restrict__ wv,const float* __restrict__ wo){
    int i=blockIdx.x*256+threadIdx.x;
    if(i<3*CC*HC){
        int w=i/(CC*HC), r=i%(CC*HC);
        const float* p=(w==0)?wq:(w==1)?wk:wv;
        u32 v=pack_hl(p[r]);                 // [c][h] natural
        g_Wh[i]=(u16)v; g_Wl[i]=(u16)(v>>16);
    } else if(i<3*CC*HC+HC*CC){
        int j=i-3*CC*HC;
        u32 v=pack_hl(wo[j]);                // [k][c] natural
        g_Woh[j]=(u16)v; g_Wol[j]=(u16)(v>>16);
    }
}

// ---------------- proj: dst[b,n,h] = sum_c src[b,c,n] * w[c,h] ---------------
__global__ __launch_bounds__(256) void proj_kernel(const float* __restrict__ rgb,
                                                   const float* __restrict__ hsi){
    extern __shared__ __align__(16) u16 sm[];
    u16 *Ah=sm, *Al=sm+64*72;            // [64n][72c-pad] planes
    float* Of=(float*)sm;                // epilogue alias [64][68]
    const int tid=threadIdx.x, w=tid>>5;
    const int n0=blockIdx.x*64, b=blockIdx.y, z=blockIdx.z;
    const float* src=((z==2)?hsi:rgb)+(size_t)b*CC*NN;
    const u16 *Wh=g_Wh+z*CC*HC, *Wl=g_Wl+z*CC*HC;
    const int r0=(w>>1)*16, c0=(w&1)*32;
    FragC acc[2];
    wmma::fill_fragment(acc[0],0.f); wmma::fill_fragment(acc[1],0.f);
    for(int cc0=0;cc0<CC;cc0+=64){
        __syncthreads();
        for(int i=tid;i<4096;i+=256){
            int c=i>>6, n=i&63;
            u32 v=pack_hl(src[(size_t)(cc0+c)*NN+n0+n]);
            Ah[n*72+c]=(u16)v; Al[n*72+c]=(u16)(v>>16);
        }
        __syncthreads();
        #pragma unroll
        for(int ks=0;ks<4;ks++){
            FragA ah,al;
            wmma::load_matrix_sync(ah,BF16P(Ah+r0*72+ks*16),72);
            wmma::load_matrix_sync(al,BF16P(Al+r0*72+ks*16),72);
            #pragma unroll
            for(int hf=0;hf<2;hf++){
                FragB bh,bl;
                wmma::load_matrix_sync(bh,BF16P(Wh+(cc0+ks*16)*HC+c0+hf*16),HC);
                wmma::load_matrix_sync(bl,BF16P(Wl+(cc0+ks*16)*HC+c0+hf*16),HC);
                MMA3(acc[hf],ah,al,bh,bl);
            }
        }
    }
    __syncthreads();
    wmma::store_matrix_sync(Of+r0*68+c0,    acc[0],68,wmma::mem_row_major);
    wmma::store_matrix_sync(Of+r0*68+c0+16, acc[1],68,wmma::mem_row_major);
    __syncthreads();
    u32* dst=(z==0?g_Q:z==1?g_K:g_V)+((size_t)b*NN+n0)*HC;
    for(int i=tid;i<4096;i+=256)
        dst[(i>>6)*HC+(i&63)] = pack_hl(Of[(i>>6)*68+(i&63)]);
}

// ---------------- attn: per (64-query tile, b); no-max softmax --------------
// S = QK^T; P = exp(S/8); O (incl. ones-col row-sums) accumulates in registers.
__global__ __launch_bounds__(128) void attn_kernel(){
    extern __shared__ __align__(16) u16 sm[];
    u16 *Qh=sm,       *Ql=Qh+4608;
    u16 *Kh=Ql+4608,  *Kl=Kh+4608;
    u16 *Vh=Kl+4608,  *Vl=Vh+5632;       // [64m][88] — cols 64..79: ones column
    u16 *Ph=Vl+5632,  *Pl=Ph+4608;
    float* Pf=(float*)Kh;                // 64*72 f32 aliases Kh+Kl exactly
    float* Of=(float*)sm;                // epilogue [64][80] over Q/K region
    const int tid=threadIdx.x, w=tid>>5;
    const int n0=blockIdx.x*64, b=blockIdx.y;
    const u32* qp=g_Q+((size_t)b*NN+n0)*HC;
    for(int i=tid;i<4096;i+=128){
        int n=i>>6,h=i&63; u32 v=qp[n*HC+h];
        Qh[n*72+h]=(u16)v; Ql[n*72+h]=(u16)(v>>16);
    }
    for(int i=tid;i<1024;i+=128){        // ones column (written once, persists)
        int m=i>>4,c=64+(i&15);
        Vh[m*88+c]=(c==64)?(u16)0x3F80:(u16)0; Vl[m*88+c]=0;
    }
    const u32 *kp=g_K+(size_t)b*NN*HC, *vp=g_V+(size_t)b*NN*HC;
    const int r0=w*16;
    FragC O[5];
    #pragma unroll
    for(int j=0;j<5;j++) wmma::fill_fragment(O[j],0.f);
    for(int m0=0;m0<NN;m0+=64){
        __syncthreads();
        for(int i=tid;i<4096;i+=128){
            int m=i>>6,h=i&63;
            u32 v=kp[(size_t)(m0+m)*HC+h]; Kh[m*72+h]=(u16)v; Kl[m*72+h]=(u16)(v>>16);
            v=vp[(size_t)(m0+m)*HC+h];     Vh[m*88+h]=(u16)v; Vl[m*88+h]=(u16)(v>>16);
        }
        __syncthreads();
        FragC S[4];
        #pragma unroll
        for(int mf=0;mf<4;mf++) wmma::fill_fragment(S[mf],0.f);
        #pragma unroll
        for(int ks=0;ks<4;ks++){
            FragA qh,ql;
            wmma::load_matrix_sync(qh,BF16P(Qh+r0*72+ks*16),72);
            wmma::load_matrix_sync(ql,BF16P(Ql+r0*72+ks*16),72);
            #pragma unroll
            for(int mf=0;mf<4;mf++){
                FragBc kh,kl;
                wmma::load_matrix_sync(kh,BF16P(Kh+mf*16*72+ks*16),72);
                wmma::load_matrix_sync(kl,BF16P(Kl+mf*16*72+ks*16),72);
                MMA3(S[mf],qh,ql,kh,kl);
            }
        }
        #pragma unroll
        for(int mf=0;mf<4;mf++)
            #pragma unroll
            for(int e=0;e<S[mf].num_elements;e++) S[mf].x[e]=ex2f(S[mf].x[e]*L2E8);
        __syncthreads();   // everyone done reading K before Pf overwrites it
        #pragma unroll
        for(int mf=0;mf<4;mf++)
            wmma::store_matrix_sync(Pf+r0*72+mf*16,S[mf],72,wmma::mem_row_major);
        __syncthreads();
        for(int i=tid;i<2048;i+=128){
            int n=i>>5, j=(i&31)*2;
            u32 v0=pack_hl(Pf[n*72+j]), v1=pack_hl(Pf[n*72+j+1]);
            Ph[n*72+j]=(u16)v0; Ph[n*72+j+1]=(u16)v1;
            Pl[n*72+j]=(u16)(v0>>16); Pl[n*72+j+1]=(u16)(v1>>16);
        }
        __syncthreads();
        #pragma unroll
        for(int ks=0;ks<4;ks++){
            FragA ph,pl;
            wmma::load_matrix_sync(ph,BF16P(Ph+r0*72+ks*16),72);
            wmma::load_matrix_sync(pl,BF16P(Pl+r0*72+ks*16),72);
            #pragma unroll
            for(int hf=0;hf<5;hf++){
                FragB vh,vl;
                wmma::load_matrix_sync(vh,BF16P(Vh+ks*16*88+hf*16),88);
                wmma::load_matrix_sync(vl,BF16P(Vl+ks*16*88+hf*16),88);
                MMA3(O[hf],ph,pl,vh,vl);
            }
        }
    }
    __syncthreads();
    #pragma unroll
    for(int hf=0;hf<5;hf++)
        wmma::store_matrix_sync(Of+r0*80+hf*16,O[hf],80,wmma::mem_row_major);
    __syncthreads();
    u32* rp=g_R+(size_t)b*NN*HC;         // [h][n] physical
    int n=tid>>1, hb=(tid&1)*32;
    float inv=1.f/Of[n*80+64];           // ones-column row sum
    #pragma unroll
    for(int j=0;j<32;j++){
        int h=hb+j;
        rp[(size_t)h*NN+n0+n]=pack_hl(Of[n*80+h]*inv);
    }
}

// ---------------- out: out[b,c,n] = sum_k res2[b,n,k] * wo[k,c] --------------
__global__ __launch_bounds__(128) void out_kernel(float* __restrict__ out){
    extern __shared__ __align__(16) u16 sm[];
    u16 *Ah=sm, *Al=sm+4608;
    const int tid=threadIdx.x, w=tid>>5;
    const int n0=blockIdx.x*64, c0=blockIdx.y*128, b=blockIdx.z;
    const u32* rp=g_R+(size_t)b*NN*HC;   // read flat as [n'][k] — the reshape
    for(int i=tid;i<4096;i+=128){
        int n=i>>6,k=i&63; u32 v=rp[(size_t)(n0+n)*HC+k];
        Ah[n*72+k]=(u16)v; Al[n*72+k]=(u16)(v>>16);
    }
    __syncthreads();
    const int r0=w*16;
    FragC acc[8];
    #pragma unroll
    for(int j=0;j<8;j++) wmma::fill_fragment(acc[j],0.f);
    #pragma unroll
    for(int ks=0;ks<4;ks++){
        FragA ah,al;
        wmma::load_matrix_sync(ah,BF16P(Ah+r0*72+ks*16),72);
        wmma::load_matrix_sync(al,BF16P(Al+r0*72+ks*16),72);
        #pragma unroll
        for(int cf=0;cf<8;cf++){
            FragB bh,bl;
            wmma::load_matrix_sync(bh,BF16P(g_Woh+(ks*16)*CC+c0+cf*16),CC);
            wmma::load_matrix_sync(bl,BF16P(g_Wol+(ks*16)*CC+c0+cf*16),CC);
            MMA3(acc[cf],ah,al,bh,bl);
        }
    }
    float* ob=out+(size_t)b*CC*NN;
    #pragma unroll
    for(int cf=0;cf<8;cf++)              // col_major store -> out[c][n] directly
        wmma::store_matrix_sync(ob+(size_t)(c0+cf*16)*NN+n0+r0, acc[cf], NN,
                                wmma::mem_col_major);
}

extern "C" void kernel_launch(void* const* d_in, const int* in_sizes, int n_in,
                              void* d_out, int out_size){
    const float* rgb=(const float*)d_in[0];
    const float* hsi=(const float*)d_in[1];
    const float* wq =(const float*)d_in[2];
    const float* wk =(const float*)d_in[3];
    const float* wv =(const float*)d_in[4];
    const float* wo =(const float*)d_in[5];
    float* out=(float*)d_out;

    const int smProj = 64*72*2*2;                     // 18432 B
    const int smAttn = (4608*4 + 5632*2 + 4608*2)*2;  // 77824 B
    const int smOut  = 64*72*2*2;                     // 18432 B
    cudaFuncSetAttribute(attn_kernel, cudaFuncAttributeMaxDynamicSharedMemorySize, smAttn);

    prep_kernel<<<512,256>>>(wq,wk,wv,wo);
    proj_kernel<<<dim3(NN/64,BB,3),256,smProj>>>(rgb,hsi);
    attn_kernel<<<dim3(NN/64,BB),128,smAttn>>>();
    out_kernel<<<dim3(NN/64,CC/128,BB),128,smOut>>>(out);
}

// round 7
// speedup vs baseline: 1.2852x; 1.0496x over previous
#include <cuda_runtime.h>
#include <cuda_bf16.h>
#include <mma.h>
using namespace nvcuda;

#define BB 16
#define CC 512
#define NN 1600
#define NP 1664
#define HC 64
#define L2E8 0.1803368801111204f

typedef unsigned int u32; typedef unsigned short u16;

// global scratch: bf16 hi/lo plane arrays (device globals; no cudaMalloc)
__device__ u16 g_Qh[BB*HC*NP], g_Ql[BB*HC*NP];   // Qt [b][h][n]
__device__ u16 g_Kh[BB*HC*NP], g_Kl[BB*HC*NP];   // Kt [b][h][m]
__device__ u16 g_Vh[BB*HC*NP], g_Vl[BB*HC*NP];   // Vt [b][h][m]
__device__ u16 g_Rh[BB*HC*NP], g_Rl[BB*HC*NP];   // resT [b][h][n] flat == res2 [n'][k]
__device__ u16 g_Wh[3*HC*CC],  g_Wl[3*HC*CC];    // wT  [z][h][c]
__device__ u16 g_Woh[CC*HC],   g_Wol[CC*HC];     // woT [c][k]

// fp32 -> (hi = truncated bf16, lo = rn bf16 of residual); packed lo16=hi, hi16=lo
__device__ __forceinline__ u32 pack_hl(float x){
    u32 h=__float_as_uint(x)&0xffff0000u; u16 lb;
    asm("cvt.rn.bf16.f32 %0,%1;":"=h"(lb):"f"(x-__uint_as_float(h)));
    return (h>>16)|((u32)lb<<16);
}
__device__ __forceinline__ float ex2f(float x){float r;asm("ex2.approx.ftz.f32 %0,%1;":"=f"(r):"f"(x));return r;}

typedef wmma::fragment<wmma::matrix_a,16,16,16,__nv_bfloat16,wmma::row_major> FragA;
typedef wmma::fragment<wmma::matrix_a,16,16,16,__nv_bfloat16,wmma::col_major> FragAc;
typedef wmma::fragment<wmma::matrix_b,16,16,16,__nv_bfloat16,wmma::row_major> FragB;
typedef wmma::fragment<wmma::matrix_b,16,16,16,__nv_bfloat16,wmma::col_major> FragBc;
typedef wmma::fragment<wmma::accumulator,16,16,16,float> FragC;
#define BF16P(p) reinterpret_cast<const __nv_bfloat16*>(p)
#define MMA3(acc, ah, al, bh, bl) do { \
    wmma::mma_sync(acc, ah, bh, acc);  \
    wmma::mma_sync(acc, al, bh, acc);  \
    wmma::mma_sync(acc, ah, bl, acc);  } while(0)

// ---------------- prep: weights -> transposed hi/lo planes; zero R pad ------
__global__ void prep_kernel(const float* __restrict__ wq,const float* __restrict__ wk,
                            const float* __restrict__ wv,const float* __restrict__ wo){
    int i=blockIdx.x*256+threadIdx.x;
    if(i<3*HC*CC){                         // wT planes [z][h][c]
        int z=i/(HC*CC), r=i%(HC*CC), h=r>>9, c=r&511;
        const float* p=(z==0)?wq:(z==1)?wk:wv;
        u32 v=pack_hl(p[c*HC+h]);
        g_Wh[i]=(u16)v; g_Wl[i]=(u16)(v>>16);
    } else if(i<3*HC*CC+CC*HC){            // woT planes [c][k]
        int j=i-3*HC*CC, c=j>>6, k=j&63;
        u32 v=pack_hl(wo[k*CC+c]);
        g_Woh[j]=(u16)v; g_Wol[j]=(u16)(v>>16);
    } else {                               // zero R pad (flat [64*1600, 64*1664) per b)
        int j=i-(3*HC*CC+CC*HC);
        if(j<BB*4096){
            int b=j>>12, t=j&4095;
            size_t o=(size_t)b*HC*NP + HC*NN + t;
            g_Rh[o]=0; g_Rl[o]=0;
        }
    }
}

// ---------------- proj: Qt/Kt[h][n]=wT@rgb (z=0), Vt=wvT@hsi (z=1) ----------
__global__ __launch_bounds__(256) void proj_kernel(const float* __restrict__ rgb,
                                                   const float* __restrict__ hsi){
    extern __shared__ u16 sm[];
    u16 *Xh=sm, *Xl=sm+64*136;             // x planes [64c][136n-pitch]
    float* Of=(float*)sm;                  // epilogue alias [64h][132n]
    const int tid=threadIdx.x, w=tid>>5;
    const int n0=blockIdx.x*128, b=blockIdx.y, z=blockIdx.z;
    const float* src=(z? hsi:rgb)+(size_t)b*CC*NN;
    const int ww=w&3, hf0=(ww&1)*2, nf0=(ww>>1)*4;
    const u16 *Ag_h, *Ag_l;
    if(z==0){ int sel=w>>2; Ag_h=g_Wh+sel*HC*CC; Ag_l=g_Wl+sel*HC*CC; }
    else    {               Ag_h=g_Wh+2*HC*CC;   Ag_l=g_Wl+2*HC*CC;   }
    const bool active=(z==0)||(w<4);
    FragC acc[2][4];
    #pragma unroll
    for(int i=0;i<2;i++)
        #pragma unroll
        for(int j=0;j<4;j++) wmma::fill_fragment(acc[i][j],0.f);
    for(int c0=0;c0<CC;c0+=64){
        __syncthreads();
        for(int i=tid;i<8192;i+=256){
            int c=i>>7, n=i&127, gn=n0+n;
            float f=(gn<NN)? src[(size_t)(c0+c)*NN+gn] : 0.f;
            u32 v=pack_hl(f);
            Xh[c*136+n]=(u16)v; Xl[c*136+n]=(u16)(v>>16);
        }
        __syncthreads();
        if(active){
            #pragma unroll
            for(int ks=0;ks<4;ks++){
                FragA ah[2],al[2];
                #pragma unroll
                for(int i=0;i<2;i++){
                    wmma::load_matrix_sync(ah[i],BF16P(Ag_h+(hf0+i)*16*CC+c0+ks*16),CC);
                    wmma::load_matrix_sync(al[i],BF16P(Ag_l+(hf0+i)*16*CC+c0+ks*16),CC);
                }
                #pragma unroll
                for(int j=0;j<4;j++){
                    FragB bh,bl;
                    wmma::load_matrix_sync(bh,BF16P(Xh+(ks*16)*136+(nf0+j)*16),136);
                    wmma::load_matrix_sync(bl,BF16P(Xl+(ks*16)*136+(nf0+j)*16),136);
                    #pragma unroll
                    for(int i=0;i<2;i++) MMA3(acc[i][j],ah[i],al[i],bh,bl);
                }
            }
        }
    }
    const int npass=(z==0)?2:1;
    for(int ps=0;ps<npass;ps++){
        __syncthreads();
        if(active && (w>>2)==ps){
            #pragma unroll
            for(int i=0;i<2;i++)
                #pragma unroll
                for(int j=0;j<4;j++)
                    wmma::store_matrix_sync(Of+((hf0+i)*16)*132+(nf0+j)*16,acc[i][j],132,wmma::mem_row_major);
        }
        __syncthreads();
        u16 *oh,*ol;
        if(z==0){ oh=ps?g_Kh:g_Qh; ol=ps?g_Kl:g_Ql; } else { oh=g_Vh; ol=g_Vl; }
        oh+=(size_t)b*HC*NP; ol+=(size_t)b*HC*NP;
        for(int i=tid;i<8192;i+=256){
            int h=i>>7, n=i&127;
            u32 v=pack_hl(Of[h*132+n]);
            oh[h*NP+n0+n]=(u16)v; ol[h*NP+n0+n]=(u16)(v>>16);
        }
    }
}

// ---------------- attn: 64q x 25x64 keys; no-max softmax; O in registers ----
__global__ __launch_bounds__(128) void attn_kernel(){
    extern __shared__ unsigned char smraw[];
    float* Pf=(float*)smraw;                   // [64][68] f32
    u16* Ph=(u16*)(smraw+17408);               // [64][72]
    u16* Pl=(u16*)(smraw+17408+9216);
    float* rsum=(float*)(smraw+17408+18432);   // [64]
    const int tid=threadIdx.x, w=tid>>5;
    const int n0=blockIdx.x*64, b=blockIdx.y;
    const size_t ob=(size_t)b*HC*NP;
    const u16 *Qhp=g_Qh+ob,*Qlp=g_Ql+ob,*Khp=g_Kh+ob,*Klp=g_Kl+ob,*Vhp=g_Vh+ob,*Vlp=g_Vl+ob;
    const int nf0=(w&1)*2, mf0=(w>>1)*2, hf0=(w>>1)*2;
    FragAc qh[2][4];                           // Q-hi cached across all iterations
    #pragma unroll
    for(int i=0;i<2;i++)
        #pragma unroll
        for(int ks=0;ks<4;ks++)
            wmma::load_matrix_sync(qh[i][ks],BF16P(Qhp+ks*16*NP+n0+(nf0+i)*16),NP);
    FragC O[2][2];
    #pragma unroll
    for(int i=0;i<2;i++){ wmma::fill_fragment(O[i][0],0.f); wmma::fill_fragment(O[i][1],0.f); }
    float rs=0.f;
    const int myn=tid>>1, mycb=(tid&1)*32;
    for(int m0=0;m0<NN;m0+=64){
        FragC S[2][2];
        #pragma unroll
        for(int i=0;i<2;i++){ wmma::fill_fragment(S[i][0],0.f); wmma::fill_fragment(S[i][1],0.f); }
        #pragma unroll
        for(int ks=0;ks<4;ks++){
            FragAc ql[2];
            #pragma unroll
            for(int i=0;i<2;i++)
                wmma::load_matrix_sync(ql[i],BF16P(Qlp+ks*16*NP+n0+(nf0+i)*16),NP);
            #pragma unroll
            for(int j=0;j<2;j++){
                FragB kh,kl;
                wmma::load_matrix_sync(kh,BF16P(Khp+ks*16*NP+m0+(mf0+j)*16),NP);
                wmma::load_matrix_sync(kl,BF16P(Klp+ks*16*NP+m0+(mf0+j)*16),NP);
                #pragma unroll
                for(int i=0;i<2;i++) MMA3(S[i][j],qh[i][ks],ql[i],kh,kl);
            }
        }
        #pragma unroll
        for(int i=0;i<2;i++)
            #pragma unroll
            for(int j=0;j<2;j++)
                #pragma unroll
                for(int e=0;e<S[i][j].num_elements;e++)
                    S[i][j].x[e]=ex2f(S[i][j].x[e]*L2E8);
        #pragma unroll
        for(int i=0;i<2;i++)
            #pragma unroll
            for(int j=0;j<2;j++)
                wmma::store_matrix_sync(Pf+(nf0+i)*16*68+(mf0+j)*16,S[i][j],68,wmma::mem_row_major);
        __syncthreads();
        {   // convert P -> bf16 planes + row-sum partials
            float s=0.f;
            #pragma unroll
            for(int c=0;c<32;c++){
                float x=Pf[myn*68+mycb+c];
                s+=x;
                u32 v=pack_hl(x);
                Ph[myn*72+mycb+c]=(u16)v; Pl[myn*72+mycb+c]=(u16)(v>>16);
            }
            rs+=s;
        }
        __syncthreads();
        #pragma unroll
        for(int ks=0;ks<4;ks++){
            FragA ph[2],pl[2];
            #pragma unroll
            for(int i=0;i<2;i++){
                wmma::load_matrix_sync(ph[i],BF16P(Ph+(nf0+i)*16*72+ks*16),72);
                wmma::load_matrix_sync(pl[i],BF16P(Pl+(nf0+i)*16*72+ks*16),72);
            }
            #pragma unroll
            for(int j=0;j<2;j++){
                FragBc vh,vl;
                wmma::load_matrix_sync(vh,BF16P(Vhp+(hf0+j)*16*NP+m0+ks*16),NP);
                wmma::load_matrix_sync(vl,BF16P(Vlp+(hf0+j)*16*NP+m0+ks*16),NP);
                #pragma unroll
                for(int i=0;i<2;i++) MMA3(O[i][j],ph[i],pl[i],vh,vl);
            }
        }
    }
    // epilogue: O -> Pf, normalize, transposed-store to resT planes
    #pragma unroll
    for(int i=0;i<2;i++)
        #pragma unroll
        for(int j=0;j<2;j++)
            wmma::store_matrix_sync(Pf+(nf0+i)*16*68+(hf0+j)*16,O[i][j],68,wmma::mem_row_major);
    float tot=rs+__shfl_xor_sync(0xffffffffu,rs,1);
    if((tid&1)==0) rsum[myn]=tot;
    __syncthreads();
    u16 *Rh=g_Rh+ob, *Rl=g_Rl+ob;
    const int n=tid&63, hg=(tid>>6)*32;
    float inv=1.f/rsum[n];
    #pragma unroll
    for(int k=0;k<32;k++){
        int h=hg+k;
        u32 v=pack_hl(Pf[n*68+h]*inv);
        Rh[h*NN+n0+n]=(u16)v; Rl[h*NN+n0+n]=(u16)(v>>16);
    }
}

// ---------------- out: out[c][n] = woT @ res2T  (all operands global) -------
__global__ __launch_bounds__(256) void out_kernel(float* __restrict__ out){
    const int tid=threadIdx.x, w=tid>>5;
    const int n0=blockIdx.x*128, c0=blockIdx.y*128, b=blockIdx.z;
    const int cf0=(w&3)*2, nf0=(w>>2)*4;   // FIXED: 8 warps cover 8cf x 8nf
    const u16* Bh=g_Rh+(size_t)b*HC*NP;    // flat read as res2 [n'][k]
    const u16* Bl=g_Rl+(size_t)b*HC*NP;
    FragC acc[2][4];
    #pragma unroll
    for(int i=0;i<2;i++)
        #pragma unroll
        for(int j=0;j<4;j++) wmma::fill_fragment(acc[i][j],0.f);
    #pragma unroll
    for(int ks=0;ks<4;ks++){
        FragA ah[2],al[2];
        #pragma unroll
        for(int i=0;i<2;i++){
            wmma::load_matrix_sync(ah[i],BF16P(g_Woh+(c0+(cf0+i)*16)*HC+ks*16),HC);
            wmma::load_matrix_sync(al[i],BF16P(g_Wol+(c0+(cf0+i)*16)*HC+ks*16),HC);
        }
        #pragma unroll
        for(int j=0;j<4;j++){
            FragBc bh,bl;
            wmma::load_matrix_sync(bh,BF16P(Bh+(size_t)(n0+(nf0+j)*16)*HC+ks*16),HC);
            wmma::load_matrix_sync(bl,BF16P(Bl+(size_t)(n0+(nf0+j)*16)*HC+ks*16),HC);
            #pragma unroll
            for(int i=0;i<2;i++) MMA3(acc[i][j],ah[i],al[i],bh,bl);
        }
    }
    float* ob=out+(size_t)b*CC*NN;
    #pragma unroll
    for(int i=0;i<2;i++)
        #pragma unroll
        for(int j=0;j<4;j++){
            int nc=n0+(nf0+j)*16;
            if(nc<NN)
                wmma::store_matrix_sync(ob+(size_t)(c0+(cf0+i)*16)*NN+nc,acc[i][j],NN,wmma::mem_row_major);
        }
}

extern "C" void kernel_launch(void* const* d_in, const int* in_sizes, int n_in,
                              void* d_out, int out_size){
    const float* rgb=(const float*)d_in[0];
    const float* hsi=(const float*)d_in[1];
    const float* wq =(const float*)d_in[2];
    const float* wk =(const float*)d_in[3];
    const float* wv =(const float*)d_in[4];
    const float* wo =(const float*)d_in[5];
    float* out=(float*)d_out;

    prep_kernel<<<768,256>>>(wq,wk,wv,wo);
    proj_kernel<<<dim3(13,BB,2),256,64*136*2*sizeof(u16)>>>(rgb,hsi);
    attn_kernel<<<dim3(25,BB),128,17408+18432+256>>>();
    out_kernel<<<dim3(13,4,BB),256>>>(out);
}

// round 9
// speedup vs baseline: 1.7324x; 1.3479x over previous
#include <cuda_runtime.h>
#include <cuda_bf16.h>
#include <mma.h>
using namespace nvcuda;

#define BB 16
#define CC 512
#define NN 1600
#define NP 1664
#define HC 64
#define L2E8 0.1803368801111204f

typedef unsigned int u32; typedef unsigned short u16;

// single TU-wide dynamic smem symbol (nvcc requires consistent redeclaration)
extern __shared__ __align__(16) unsigned char smdyn[];

// global scratch: bf16 hi/lo plane arrays
__device__ u16 g_Qh[BB*NP*HC], g_Ql[BB*NP*HC];   // Q [b][n][h]  (natural)
__device__ u16 g_Kh[BB*NP*HC], g_Kl[BB*NP*HC];   // K [b][m][h]  (natural)
__device__ u16 g_Vh[BB*HC*NP], g_Vl[BB*HC*NP];   // Vt [b][h][m]
__device__ u16 g_Rh[BB*HC*NP], g_Rl[BB*HC*NP];   // resT [b][h][n] flat == res2 [n'][k]
__device__ u16 g_Wh[3*HC*CC],  g_Wl[3*HC*CC];    // wT  [z][h][c]
__device__ u16 g_Woh[CC*HC],   g_Wol[CC*HC];     // woT [c][k]

__device__ __forceinline__ u32 pack_hl(float x){
    u32 h=__float_as_uint(x)&0xffff0000u; u16 lb;
    asm("cvt.rn.bf16.f32 %0,%1;":"=h"(lb):"f"(x-__uint_as_float(h)));
    return (h>>16)|((u32)lb<<16);
}
__device__ __forceinline__ void split2(float x0,float x1,u32& hi,u32& lo){
    u32 h0=__float_as_uint(x0)&0xffff0000u, h1=__float_as_uint(x1)&0xffff0000u;
    hi=(h0>>16)|h1;
    float l0=x0-__uint_as_float(h0), l1=x1-__uint_as_float(h1);
    asm("cvt.rn.bf16x2.f32 %0,%1,%2;":"=r"(lo):"f"(l1),"f"(l0));
}
__device__ __forceinline__ float ex2f(float x){float r;asm("ex2.approx.ftz.f32 %0,%1;":"=f"(r):"f"(x));return r;}
__device__ __forceinline__ u32 s2u(const void* p){u32 a;asm("{.reg .u64 t; cvta.to.shared.u64 t,%1; cvt.u32.u64 %0,t;}":"=r"(a):"l"(p));return a;}
__device__ __forceinline__ void mmabf(float (&c)[4], u32 a0,u32 a1,u32 a2,u32 a3, u32 b0,u32 b1){
    asm volatile("mma.sync.aligned.m16n8k16.row.col.f32.bf16.bf16.f32 "
        "{%0,%1,%2,%3},{%4,%5,%6,%7},{%8,%9},{%0,%1,%2,%3};"
        : "+f"(c[0]),"+f"(c[1]),"+f"(c[2]),"+f"(c[3])
        : "r"(a0),"r"(a1),"r"(a2),"r"(a3),"r"(b0),"r"(b1));
}
__device__ __forceinline__ void ldsm4(u32 (&r)[4], u32 a){
    asm volatile("ldmatrix.sync.aligned.m8n8.x4.shared.b16 {%0,%1,%2,%3},[%4];"
        :"=r"(r[0]),"=r"(r[1]),"=r"(r[2]),"=r"(r[3]):"r"(a));
}

typedef wmma::fragment<wmma::matrix_a,16,16,16,__nv_bfloat16,wmma::row_major> FragA;
typedef wmma::fragment<wmma::matrix_b,16,16,16,__nv_bfloat16,wmma::row_major> FragB;
typedef wmma::fragment<wmma::matrix_b,16,16,16,__nv_bfloat16,wmma::col_major> FragBc;
typedef wmma::fragment<wmma::accumulator,16,16,16,float> FragC;
#define BF16P(p) reinterpret_cast<const __nv_bfloat16*>(p)
#define MMA3(acc, ah, al, bh, bl) do { \
    wmma::mma_sync(acc, ah, bh, acc);  \
    wmma::mma_sync(acc, al, bh, acc);  \
    wmma::mma_sync(acc, ah, bl, acc);  } while(0)

// ---------------- prep ----------------
__global__ void prep_kernel(const float* __restrict__ wq,const float* __restrict__ wk,
                            const float* __restrict__ wv,const float* __restrict__ wo){
    int i=blockIdx.x*256+threadIdx.x;
    if(i<3*HC*CC){
        int z=i/(HC*CC), r=i%(HC*CC), h=r>>9, c=r&511;
        const float* p=(z==0)?wq:(z==1)?wk:wv;
        u32 v=pack_hl(p[c*HC+h]);
        g_Wh[i]=(u16)v; g_Wl[i]=(u16)(v>>16);
    } else if(i<3*HC*CC+CC*HC){
        int j=i-3*HC*CC, c=j>>6, k=j&63;
        u32 v=pack_hl(wo[k*CC+c]);
        g_Woh[j]=(u16)v; g_Wol[j]=(u16)(v>>16);
    } else {
        int j=i-(3*HC*CC+CC*HC);
        if(j<BB*4096){
            int b=j>>12, t=j&4095;
            size_t o=(size_t)b*HC*NP + HC*NN + t;
            g_Rh[o]=0; g_Rl[o]=0;
        }
    }
}

// ---------------- proj (wmma; z=0 -> Q,K natural; z=1 -> Vt) ----------------
__global__ __launch_bounds__(256) void proj_kernel(const float* __restrict__ rgb,
                                                   const float* __restrict__ hsi){
    u16 *Xh=(u16*)smdyn, *Xl=(u16*)smdyn+64*136;
    float* Of=(float*)smdyn;
    const int tid=threadIdx.x, w=tid>>5;
    const int n0=blockIdx.x*128, b=blockIdx.y, z=blockIdx.z;
    const float* src=(z? hsi:rgb)+(size_t)b*CC*NN;
    const int ww=w&3, hf0=(ww&1)*2, nf0=(ww>>1)*4;
    const u16 *Ag_h, *Ag_l;
    if(z==0){ int sel=w>>2; Ag_h=g_Wh+sel*HC*CC; Ag_l=g_Wl+sel*HC*CC; }
    else    {               Ag_h=g_Wh+2*HC*CC;   Ag_l=g_Wl+2*HC*CC;   }
    const bool active=(z==0)||(w<4);
    FragC acc[2][4];
    #pragma unroll
    for(int i=0;i<2;i++)
        #pragma unroll
        for(int j=0;j<4;j++) wmma::fill_fragment(acc[i][j],0.f);
    for(int c0=0;c0<CC;c0+=64){
        __syncthreads();
        for(int i=tid;i<8192;i+=256){
            int c=i>>7, n=i&127, gn=n0+n;
            float f=(gn<NN)? src[(size_t)(c0+c)*NN+gn] : 0.f;
            u32 v=pack_hl(f);
            Xh[c*136+n]=(u16)v; Xl[c*136+n]=(u16)(v>>16);
        }
        __syncthreads();
        if(active){
            #pragma unroll
            for(int ks=0;ks<4;ks++){
                FragA ah[2],al[2];
                #pragma unroll
                for(int i=0;i<2;i++){
                    wmma::load_matrix_sync(ah[i],BF16P(Ag_h+(hf0+i)*16*CC+c0+ks*16),CC);
                    wmma::load_matrix_sync(al[i],BF16P(Ag_l+(hf0+i)*16*CC+c0+ks*16),CC);
                }
                #pragma unroll
                for(int j=0;j<4;j++){
                    FragB bh,bl;
                    wmma::load_matrix_sync(bh,BF16P(Xh+(ks*16)*136+(nf0+j)*16),136);
                    wmma::load_matrix_sync(bl,BF16P(Xl+(ks*16)*136+(nf0+j)*16),136);
                    #pragma unroll
                    for(int i=0;i<2;i++) MMA3(acc[i][j],ah[i],al[i],bh,bl);
                }
            }
        }
    }
    const int npass=(z==0)?2:1;
    for(int ps=0;ps<npass;ps++){
        __syncthreads();
        if(active && (w>>2)==ps){
            #pragma unroll
            for(int i=0;i<2;i++)
                #pragma unroll
                for(int j=0;j<4;j++)
                    wmma::store_matrix_sync(Of+((hf0+i)*16)*132+(nf0+j)*16,acc[i][j],132,wmma::mem_row_major);
        }
        __syncthreads();
        u16 *oh,*ol;
        if(z==0){ oh=ps?g_Kh:g_Qh; ol=ps?g_Kl:g_Ql; } else { oh=g_Vh; ol=g_Vl; }
        oh+=(size_t)b*NP*HC; ol+=(size_t)b*NP*HC;
        if(z==0){
            for(int i=tid;i<8192;i+=256){
                int n=i>>6, h=i&63;
                u32 v=pack_hl(Of[h*132+n]);
                oh[(size_t)(n0+n)*HC+h]=(u16)v; ol[(size_t)(n0+n)*HC+h]=(u16)(v>>16);
            }
        } else {
            for(int i=tid;i<8192;i+=256){
                int h=i>>7, n=i&127;
                u32 v=pack_hl(Of[h*132+n]);
                oh[(size_t)h*NP+n0+n]=(u16)v; ol[(size_t)h*NP+n0+n]=(u16)(v>>16);
            }
        }
    }
}

// ---------------- attn: FA2-style mma.sync, register-resident P -------------
#define TILEB 9216           // one 64x72 u16 plane
#define BUFB  36864          // 4 planes per buffer
__global__ __launch_bounds__(256) void attn_kernel(){
    unsigned char* sm=smdyn;
    const int tid=threadIdx.x, lane=tid&31, warp=tid>>5;
    const int n0=blockIdx.x*128, b=blockIdx.y;
    const size_t qb=(size_t)b*NP*HC, vb=(size_t)b*HC*NP;
    const u16 *Qhp=g_Qh+qb,*Qlp=g_Ql+qb,*Khp=g_Kh+qb,*Klp=g_Kl+qb;
    const u16 *Vhp=g_Vh+vb,*Vlp=g_Vl+vb;
    const u32 smb=s2u(sm);
    // cached Q fragments (A-layout, m16k16), hi+lo
    const int q0=n0+warp*16, r4=lane>>2, c2=(lane&3)*2;
    u32 qh[4][4], ql[4][4];
    #pragma unroll
    for(int ks=0;ks<4;ks++){
        size_t o00=(size_t)(q0+r4)*HC+ks*16+c2, o10=o00+8*HC, o01=o00+8, o11=o10+8;
        qh[ks][0]=*(const u32*)(Qhp+o00); qh[ks][1]=*(const u32*)(Qhp+o10);
        qh[ks][2]=*(const u32*)(Qhp+o01); qh[ks][3]=*(const u32*)(Qhp+o11);
        ql[ks][0]=*(const u32*)(Qlp+o00); ql[ks][1]=*(const u32*)(Qlp+o10);
        ql[ks][2]=*(const u32*)(Qlp+o01); ql[ks][3]=*(const u32*)(Qlp+o11);
    }
    // ldmatrix lane constants
    const int mat=lane>>3, mr=((mat>>1)<<3)+(lane&7), hoff=(mat&1)<<3;
    float O[8][4];
    #pragma unroll
    for(int j=0;j<8;j++){O[j][0]=0;O[j][1]=0;O[j][2]=0;O[j][3]=0;}
    float rsA=0.f, rsB=0.f;
    // tile loader: K[m][h] + Vt[h][m] hi/lo into buffer
    auto loadt=[&](int m0, unsigned char* buf){
        u32* kh=(u32*)buf; u32* kl=(u32*)(buf+TILEB);
        u32* vh=(u32*)(buf+2*TILEB); u32* vl=(u32*)(buf+3*TILEB);
        #pragma unroll
        for(int t=0;t<8;t++){
            int i=tid+t*256, r=i>>5, w=i&31;
            kh[r*36+w]=((const u32*)(Khp+(size_t)(m0+r)*HC))[w];
            kl[r*36+w]=((const u32*)(Klp+(size_t)(m0+r)*HC))[w];
            vh[r*36+w]=((const u32*)(Vhp+(size_t)r*NP+m0))[w];
            vl[r*36+w]=((const u32*)(Vlp+(size_t)r*NP+m0))[w];
        }
    };
    loadt(0, sm);
    __syncthreads();
    for(int it=0; it<25; it++){
        const int bsel=it&1;
        if(it<24) loadt((it+1)*64, sm+(bsel^1)*BUFB);
        const u32 kb=smb+bsel*BUFB;
        u32 Ph[4][4], Pl[4][4];
        #pragma unroll
        for(int jj=0;jj<4;jj++){
            float c0[4]={0,0,0,0}, c1[4]={0,0,0,0};
            #pragma unroll
            for(int ks=0;ks<4;ks++){
                u32 kh4[4],kl4[4];
                u32 a=kb+(((jj*16+mr)*72)+ks*16+hoff)*2;
                ldsm4(kh4,a); ldsm4(kl4,a+TILEB);
                mmabf(c0,qh[ks][0],qh[ks][1],qh[ks][2],qh[ks][3],kh4[0],kh4[1]);
                mmabf(c1,qh[ks][0],qh[ks][1],qh[ks][2],qh[ks][3],kh4[2],kh4[3]);
                mmabf(c0,ql[ks][0],ql[ks][1],ql[ks][2],ql[ks][3],kh4[0],kh4[1]);
                mmabf(c1,ql[ks][0],ql[ks][1],ql[ks][2],ql[ks][3],kh4[2],kh4[3]);
                mmabf(c0,qh[ks][0],qh[ks][1],qh[ks][2],qh[ks][3],kl4[0],kl4[1]);
                mmabf(c1,qh[ks][0],qh[ks][1],qh[ks][2],qh[ks][3],kl4[2],kl4[3]);
            }
            #pragma unroll
            for(int e=0;e<4;e++){ c0[e]=ex2f(c0[e]*L2E8); c1[e]=ex2f(c1[e]*L2E8); }
            rsA += (c0[0]+c0[1])+(c1[0]+c1[1]);
            rsB += (c0[2]+c0[3])+(c1[2]+c1[3]);
            split2(c0[0],c0[1],Ph[jj][0],Pl[jj][0]);
            split2(c0[2],c0[3],Ph[jj][1],Pl[jj][1]);
            split2(c1[0],c1[1],Ph[jj][2],Pl[jj][2]);
            split2(c1[2],c1[3],Ph[jj][3],Pl[jj][3]);
        }
        #pragma unroll
        for(int jj=0;jj<4;jj++){
            #pragma unroll
            for(int hh=0;hh<4;hh++){
                u32 vh4[4],vl4[4];
                u32 a=kb+2*TILEB+(((hh*16+mr)*72)+jj*16+hoff)*2;
                ldsm4(vh4,a); ldsm4(vl4,a+TILEB);
                mmabf(O[hh*2],  Ph[jj][0],Ph[jj][1],Ph[jj][2],Ph[jj][3],vh4[0],vh4[1]);
                mmabf(O[hh*2+1],Ph[jj][0],Ph[jj][1],Ph[jj][2],Ph[jj][3],vh4[2],vh4[3]);
                mmabf(O[hh*2],  Pl[jj][0],Pl[jj][1],Pl[jj][2],Pl[jj][3],vh4[0],vh4[1]);
                mmabf(O[hh*2+1],Pl[jj][0],Pl[jj][1],Pl[jj][2],Pl[jj][3],vh4[2],vh4[3]);
                mmabf(O[hh*2],  Ph[jj][0],Ph[jj][1],Ph[jj][2],Ph[jj][3],vl4[0],vl4[1]);
                mmabf(O[hh*2+1],Ph[jj][0],Ph[jj][1],Ph[jj][2],Ph[jj][3],vl4[2],vl4[3]);
            }
        }
        __syncthreads();
    }
    // row sums: reduce over lane&3 group
    rsA += __shfl_xor_sync(0xffffffffu,rsA,1); rsA += __shfl_xor_sync(0xffffffffu,rsA,2);
    rsB += __shfl_xor_sync(0xffffffffu,rsB,1); rsB += __shfl_xor_sync(0xffffffffu,rsB,2);
    const float invA=1.f/rsA, invB=1.f/rsB;
    float* Of=(float*)sm;   // [128 q][68]
    #pragma unroll
    for(int j=0;j<8;j++){
        int h=j*8+c2;
        Of[(warp*16+r4)*68+h  ]=O[j][0]*invA;
        Of[(warp*16+r4)*68+h+1]=O[j][1]*invA;
        Of[(warp*16+r4+8)*68+h  ]=O[j][2]*invB;
        Of[(warp*16+r4+8)*68+h+1]=O[j][3]*invB;
    }
    __syncthreads();
    u16 *Rh=g_Rh+(size_t)b*HC*NP, *Rl=g_Rl+(size_t)b*HC*NP;
    for(int i=tid;i<8192;i+=256){
        int h=i>>7, n=i&127, gn=n0+n;
        if(gn<NN){
            u32 v=pack_hl(Of[n*68+h]);
            Rh[(size_t)h*NN+gn]=(u16)v; Rl[(size_t)h*NN+gn]=(u16)(v>>16);
        }
    }
}

// ---------------- out: unchanged (wmma, global operands) --------------------
__global__ __launch_bounds__(256) void out_kernel(float* __restrict__ out){
    const int tid=threadIdx.x, w=tid>>5;
    const int n0=blockIdx.x*128, c0=blockIdx.y*128, b=blockIdx.z;
    const int cf0=(w&3)*2, nf0=(w>>2)*4;
    const u16* Bh=g_Rh+(size_t)b*HC*NP;
    const u16* Bl=g_Rl+(size_t)b*HC*NP;
    FragC acc[2][4];
    #pragma unroll
    for(int i=0;i<2;i++)
        #pragma unroll
        for(int j=0;j<4;j++) wmma::fill_fragment(acc[i][j],0.f);
    #pragma unroll
    for(int ks=0;ks<4;ks++){
        FragA ah[2],al[2];
        #pragma unroll
        for(int i=0;i<2;i++){
            wmma::load_matrix_sync(ah[i],BF16P(g_Woh+(c0+(cf0+i)*16)*HC+ks*16),HC);
            wmma::load_matrix_sync(al[i],BF16P(g_Wol+(c0+(cf0+i)*16)*HC+ks*16),HC);
        }
        #pragma unroll
        for(int j=0;j<4;j++){
            FragBc bh,bl;
            wmma::load_matrix_sync(bh,BF16P(Bh+(size_t)(n0+(nf0+j)*16)*HC+ks*16),HC);
            wmma::load_matrix_sync(bl,BF16P(Bl+(size_t)(n0+(nf0+j)*16)*HC+ks*16),HC);
            #pragma unroll
            for(int i=0;i<2;i++) MMA3(acc[i][j],ah[i],al[i],bh,bl);
        }
    }
    float* ob=out+(size_t)b*CC*NN;
    #pragma unroll
    for(int i=0;i<2;i++)
        #pragma unroll
        for(int j=0;j<4;j++){
            int nc=n0+(nf0+j)*16;
            if(nc<NN)
                wmma::store_matrix_sync(ob+(size_t)(c0+(cf0+i)*16)*NN+nc,acc[i][j],NN,wmma::mem_row_major);
        }
}

extern "C" void kernel_launch(void* const* d_in, const int* in_sizes, int n_in,
                              void* d_out, int out_size){
    const float* rgb=(const float*)d_in[0];
    const float* hsi=(const float*)d_in[1];
    const float* wq =(const float*)d_in[2];
    const float* wk =(const float*)d_in[3];
    const float* wv =(const float*)d_in[4];
    const float* wo =(const float*)d_in[5];
    float* out=(float*)d_out;

    cudaFuncSetAttribute(attn_kernel, cudaFuncAttributeMaxDynamicSharedMemorySize, 2*BUFB);
    prep_kernel<<<768,256>>>(wq,wk,wv,wo);
    proj_kernel<<<dim3(13,BB,2),256,64*136*2*sizeof(u16)>>>(rgb,hsi);
    attn_kernel<<<dim3(13,BB),256,2*BUFB>>>();
    out_kernel<<<dim3(13,4,BB),256>>>(out);
}